// round 9
// baseline (speedup 1.0000x reference)
#include <cuda_runtime.h>
#include <cuda_bf16.h>
#include <math.h>

#define BB 64
#define LL 1024
#define HH 64
#define H2 128
#define VV 32000
#define TOK 128
#define HPAD 68

// Scratch (device globals; no allocation allowed)
__device__ float  g_kall[BB * LL * HH];   // 16 MB
__device__ float4 g_meta[BB * LL];        // (rinv, 0.16*kk, dot(k_t,k_{t+1}), dot(k_t,k_{t+2}))
__device__ float  g_r2[BB * HH];

// ---------------------------------------------------------------------------
// Kernel 1: per-token front-end (measured-best r2 config: 512 thr, 128 tok)
// ---------------------------------------------------------------------------
__global__ void __launch_bounds__(512) k1_frontend(
        const int* __restrict__ seq, const float* __restrict__ embed,
        const float* __restrict__ W1, const float* __restrict__ b1,
        const float* __restrict__ W2, const float* __restrict__ b2,
        const float* __restrict__ gamma, const float* __restrict__ beta,
        const float* __restrict__ kpW) {
    extern __shared__ float sm[];
    float* h_sm  = sm;
    float* w1_sm = h_sm  + TOK * HPAD;
    float* u_sm  = w1_sm + HH * H2;
    float* w2_sm = u_sm  + TOK * H2;
    float* kp_sm = w2_sm + H2 * HH;
    float* b1s   = kp_sm + HH * HH;
    float* b2s   = b1s + H2;
    float* gsm   = b2s + HH;
    float* bsm   = gsm + HH;

    const int tid  = threadIdx.x;
    const int tok0 = blockIdx.x * TOK;

    for (int idx = tid; idx < HH * H2; idx += 512) w1_sm[idx] = W1[idx];
    for (int idx = tid; idx < H2 * HH; idx += 512) w2_sm[idx] = W2[idx];
    for (int idx = tid; idx < HH * HH; idx += 512) kp_sm[idx] = kpW[idx];
    if (tid < H2) b1s[tid] = b1[tid];
    if (tid < HH) { b2s[tid] = b2[tid]; gsm[tid] = gamma[tid]; bsm[tid] = beta[tid]; }

    #pragma unroll
    for (int k = 0; k < 16; k++) {
        int idx = tid + 512 * k;
        int t = idx >> 6, j = idx & 63;
        int row = seq[tok0 + t];
        h_sm[t * HPAD + j] = embed[row * HH + j];
    }
    __syncthreads();

    const int tt = tid >> 4;
    const int ct = tid & 15;

    // GEMM1
    {
        const int r0 = tt * 4, c0 = ct * 8;
        float acc[4][8];
        #pragma unroll
        for (int r = 0; r < 4; r++)
            #pragma unroll
            for (int c = 0; c < 8; c++) acc[r][c] = 0.f;
        #pragma unroll 2
        for (int j4 = 0; j4 < HH; j4 += 4) {
            float hv[4][4];
            #pragma unroll
            for (int r = 0; r < 4; r++)
                *(float4*)hv[r] = *(const float4*)&h_sm[(r0 + r) * HPAD + j4];
            #pragma unroll
            for (int jj = 0; jj < 4; jj++) {
                float4 wA = *(const float4*)&w1_sm[(j4 + jj) * H2 + c0];
                float4 wB = *(const float4*)&w1_sm[(j4 + jj) * H2 + c0 + 4];
                #pragma unroll
                for (int r = 0; r < 4; r++) {
                    float hvv = hv[r][jj];
                    acc[r][0] = fmaf(hvv, wA.x, acc[r][0]);
                    acc[r][1] = fmaf(hvv, wA.y, acc[r][1]);
                    acc[r][2] = fmaf(hvv, wA.z, acc[r][2]);
                    acc[r][3] = fmaf(hvv, wA.w, acc[r][3]);
                    acc[r][4] = fmaf(hvv, wB.x, acc[r][4]);
                    acc[r][5] = fmaf(hvv, wB.y, acc[r][5]);
                    acc[r][6] = fmaf(hvv, wB.z, acc[r][6]);
                    acc[r][7] = fmaf(hvv, wB.w, acc[r][7]);
                }
            }
        }
        #pragma unroll
        for (int r = 0; r < 4; r++)
            #pragma unroll
            for (int c = 0; c < 8; c++)
                u_sm[(r0 + r) * H2 + c0 + c] = fmaxf(acc[r][c] + b1s[c0 + c], 0.f);
    }
    __syncthreads();

    // GEMM2 + residual
    {
        const int r0 = tt * 4, c0 = ct * 4;
        float acc[4][4];
        #pragma unroll
        for (int r = 0; r < 4; r++)
            #pragma unroll
            for (int c = 0; c < 4; c++) acc[r][c] = 0.f;
        #pragma unroll 2
        for (int j4 = 0; j4 < H2; j4 += 4) {
            float uv[4][4];
            #pragma unroll
            for (int r = 0; r < 4; r++)
                *(float4*)uv[r] = *(const float4*)&u_sm[(r0 + r) * H2 + j4];
            #pragma unroll
            for (int jj = 0; jj < 4; jj++) {
                float4 w = *(const float4*)&w2_sm[(j4 + jj) * HH + c0];
                #pragma unroll
                for (int r = 0; r < 4; r++) {
                    float uvv = uv[r][jj];
                    acc[r][0] = fmaf(uvv, w.x, acc[r][0]);
                    acc[r][1] = fmaf(uvv, w.y, acc[r][1]);
                    acc[r][2] = fmaf(uvv, w.z, acc[r][2]);
                    acc[r][3] = fmaf(uvv, w.w, acc[r][3]);
                }
            }
        }
        #pragma unroll
        for (int r = 0; r < 4; r++)
            #pragma unroll
            for (int c = 0; c < 4; c++)
                h_sm[(r0 + r) * HPAD + c0 + c] += acc[r][c] + b2s[c0 + c];
    }
    __syncthreads();

    // LayerNorm per token
    if (tid < TOK) {
        float s = 0.f, ss = 0.f;
        #pragma unroll 8
        for (int j = 0; j < HH; j++) {
            float x = h_sm[tid * HPAD + j];
            s += x; ss += x * x;
        }
        float mu = s * (1.f / HH);
        float var = ss * (1.f / HH) - mu * mu;
        float rs = rsqrtf(var + 1e-5f);
        #pragma unroll 8
        for (int j = 0; j < HH; j++) {
            float x = h_sm[tid * HPAD + j];
            h_sm[tid * HPAD + j] = (x - mu) * rs * gsm[j] + bsm[j];
        }
    }
    __syncthreads();

    // GEMM3 -> g_kall
    {
        const int r0 = tt * 4, c0 = ct * 4;
        float acc[4][4];
        #pragma unroll
        for (int r = 0; r < 4; r++)
            #pragma unroll
            for (int c = 0; c < 4; c++) acc[r][c] = 0.f;
        #pragma unroll 2
        for (int j4 = 0; j4 < HH; j4 += 4) {
            float hv[4][4];
            #pragma unroll
            for (int r = 0; r < 4; r++)
                *(float4*)hv[r] = *(const float4*)&h_sm[(r0 + r) * HPAD + j4];
            #pragma unroll
            for (int jj = 0; jj < 4; jj++) {
                float4 w = *(const float4*)&kp_sm[(j4 + jj) * HH + c0];
                #pragma unroll
                for (int r = 0; r < 4; r++) {
                    float hvv = hv[r][jj];
                    acc[r][0] = fmaf(hvv, w.x, acc[r][0]);
                    acc[r][1] = fmaf(hvv, w.y, acc[r][1]);
                    acc[r][2] = fmaf(hvv, w.z, acc[r][2]);
                    acc[r][3] = fmaf(hvv, w.w, acc[r][3]);
                }
            }
        }
        #pragma unroll
        for (int r = 0; r < 4; r++)
            #pragma unroll
            for (int c = 0; c < 4; c++)
                g_kall[(tok0 + r0 + r) * HH + c0 + c] = acc[r][c];
    }
}

// ---------------------------------------------------------------------------
// Kernel 1b: per-(b,t) metadata: (rinv, 0.16*kk, dot(k_t,k_{t+1}), dot(k_t,k_{t+2}))
// ---------------------------------------------------------------------------
__global__ void k1b_meta() {
    const int g    = blockIdx.x * 8 + (threadIdx.x >> 5);
    const int lane = threadIdx.x & 31;
    const int b = g >> 10, t = g & 1023;
    if (t >= LL - 1) return;
    const float* kt = g_kall + (b * LL + t) * HH;
    float2 k0 = *(const float2*)&kt[lane * 2];
    float2 k1 = *(const float2*)&kt[HH + lane * 2];
    float2 k2v = make_float2(0.f, 0.f);
    if (t + 2 <= LL - 1) k2v = *(const float2*)&kt[2 * HH + lane * 2];
    float pkk = k0.x * k0.x + k0.y * k0.y;
    float pd1 = k0.x * k1.x + k0.y * k1.y;
    float pd2 = k0.x * k2v.x + k0.y * k2v.y;
    #pragma unroll
    for (int off = 16; off; off >>= 1) {
        pkk += __shfl_xor_sync(0xffffffffu, pkk, off);
        pd1 += __shfl_xor_sync(0xffffffffu, pd1, off);
        pd2 += __shfl_xor_sync(0xffffffffu, pd2, off);
    }
    if (lane == 0) {
        float rinv = 1.0f / fmaxf(sqrtf(pkk), 1e-12f);
        g_meta[b * LL + t] = make_float4(rinv, 0.16f * pkk, pd1, pd2);
    }
}

// ---------------------------------------------------------------------------
// Kernel 2: 64-thread scan, lag-2 pipeline, SOFTWARE-PIPELINED body:
// the fused (update+matvec) M-pass is split into four 16-col strips with one
// butterfly SHFL level between strips, so SHFL latency is hidden under FMAs.
// Update applied unconditionally with gs2 (0 when ungated); kbuf zero-init.
// ---------------------------------------------------------------------------
__global__ void __launch_bounds__(64, 1) k2_scan(const float* __restrict__ rpW,
                                                 const float* __restrict__ rpb) {
    const int b = blockIdx.x;
    const int i = threadIdx.x;
    const int w = i >> 5;
    __shared__ __align__(16) float kbuf[8][64];
    __shared__ float wsum[2][2];
    __shared__ float rds[64];

    float M[64];
    #pragma unroll
    for (int j = 0; j < 64; j++) M[j] = 0.f;

    const float*  kb = g_kall + b * LL * HH;
    const float4* mb = g_meta + b * LL;

    // zero all kbuf slots (slots 6,7 are read as "k^{t-2}" at t=0,1 with gs2=0;
    // must not contain NaN bit patterns)
    #pragma unroll
    for (int sl = 0; sl < 8; sl++) kbuf[sl][i] = 0.f;

    float kc_cur = kb[i];            // k^0_i
    float kc_nxt = kb[HH + i];       // k^1_i
    float xA     = kb[2 * HH + i];   // k^2_i (published at iter 0)
    kbuf[0][i] = kc_cur;
    kbuf[1][i] = kc_nxt;
    float4 mt = mb[0];
    float a = 0.f;
    float gs1 = 0.f, gs2 = 0.f;      // s_{t-1}, s_{t-2} (gated err_i*rinv)
    float d1 = 0.f, d2 = 0.f, w_prev = 0.f;
    __syncthreads();

    for (int t = 0; t < LL - 1; t++) {
        float xB = (t <= LL - 4) ? kb[(t + 3) * HH + i] : 0.f;
        float4 mtn = mb[t + 1];
        const int p = t & 1;

        // ---- critical-path scalars -------------------------------------
        float vpk = fmaf(gs2, d2, fmaf(gs1, d1, a));
        float err = fmaf(-mt.x, vpk, kc_cur);      // k_i - rinv*vpk_i
        float s   = err * mt.x;                    // candidate update scalar
        float perr = err * err;

        kbuf[(t + 2) & 7][i] = xA;                 // publish k^{t+2} (independent)

        const float* kp = kbuf[(t - 2) & 7];       // k^{t-2} (update vector)
        const float* kn = kbuf[(t + 1) & 7];       // k^{t+1} (matvec operand)
        float v0 = 0.f, v1 = 0.f, v2 = 0.f, v3 = 0.f;

        // ---- strip 0 (j 0..15), then butterfly level 16 ----------------
        #pragma unroll
        for (int j = 0; j < 16; j += 4) {
            float4 kp4 = *(const float4*)&kp[j];
            float4 kn4 = *(const float4*)&kn[j];
            M[j]     = fmaf(gs2, kp4.x, M[j]);     v0 = fmaf(M[j],     kn4.x, v0);
            M[j + 1] = fmaf(gs2, kp4.y, M[j + 1]); v1 = fmaf(M[j + 1], kn4.y, v1);
            M[j + 2] = fmaf(gs2, kp4.z, M[j + 2]); v2 = fmaf(M[j + 2], kn4.z, v2);
            M[j + 3] = fmaf(gs2, kp4.w, M[j + 3]); v3 = fmaf(M[j + 3], kn4.w, v3);
        }
        perr += __shfl_xor_sync(0xffffffffu, perr, 16);

        // ---- strip 1 (j 16..31), butterfly level 8 ---------------------
        #pragma unroll
        for (int j = 16; j < 32; j += 4) {
            float4 kp4 = *(const float4*)&kp[j];
            float4 kn4 = *(const float4*)&kn[j];
            M[j]     = fmaf(gs2, kp4.x, M[j]);     v0 = fmaf(M[j],     kn4.x, v0);
            M[j + 1] = fmaf(gs2, kp4.y, M[j + 1]); v1 = fmaf(M[j + 1], kn4.y, v1);
            M[j + 2] = fmaf(gs2, kp4.z, M[j + 2]); v2 = fmaf(M[j + 2], kn4.z, v2);
            M[j + 3] = fmaf(gs2, kp4.w, M[j + 3]); v3 = fmaf(M[j + 3], kn4.w, v3);
        }
        perr += __shfl_xor_sync(0xffffffffu, perr, 8);

        // ---- strip 2 (j 32..47), butterfly level 4 ---------------------
        #pragma unroll
        for (int j = 32; j < 48; j += 4) {
            float4 kp4 = *(const float4*)&kp[j];
            float4 kn4 = *(const float4*)&kn[j];
            M[j]     = fmaf(gs2, kp4.x, M[j]);     v0 = fmaf(M[j],     kn4.x, v0);
            M[j + 1] = fmaf(gs2, kp4.y, M[j + 1]); v1 = fmaf(M[j + 1], kn4.y, v1);
            M[j + 2] = fmaf(gs2, kp4.z, M[j + 2]); v2 = fmaf(M[j + 2], kn4.z, v2);
            M[j + 3] = fmaf(gs2, kp4.w, M[j + 3]); v3 = fmaf(M[j + 3], kn4.w, v3);
        }
        perr += __shfl_xor_sync(0xffffffffu, perr, 4);

        // ---- strip 3 (j 48..63), butterfly levels 2,1 ------------------
        #pragma unroll
        for (int j = 48; j < 64; j += 4) {
            float4 kp4 = *(const float4*)&kp[j];
            float4 kn4 = *(const float4*)&kn[j];
            M[j]     = fmaf(gs2, kp4.x, M[j]);     v0 = fmaf(M[j],     kn4.x, v0);
            M[j + 1] = fmaf(gs2, kp4.y, M[j + 1]); v1 = fmaf(M[j + 1], kn4.y, v1);
            M[j + 2] = fmaf(gs2, kp4.z, M[j + 2]); v2 = fmaf(M[j + 2], kn4.z, v2);
            M[j + 3] = fmaf(gs2, kp4.w, M[j + 3]); v3 = fmaf(M[j + 3], kn4.w, v3);
        }
        perr += __shfl_xor_sync(0xffffffffu, perr, 2);
        perr += __shfl_xor_sync(0xffffffffu, perr, 1);
        if ((i & 31) == 0) wsum[p][w] = perr;

        a = (v0 + v1) + (v2 + v3);                 // matvec result: M_{t-2}@k^{t+1}

        // ---- barrier, finalize gate_t, shift the pipeline --------------
        __syncthreads();
        float errsum = wsum[p][0] + wsum[p][1];
        int gate = errsum >= mt.y;                 // ||err||^2 >= 0.16*||k||^2
        gs2 = gs1;
        gs1 = gate ? s : 0.f;
        d2 = w_prev;            // D(t-1, t+1) = meta[t-1].w
        d1 = mt.z;              // D(t,   t+1) = meta[t].z
        w_prev = mt.w;
        mt = mtn;
        kc_cur = kc_nxt; kc_nxt = xA; xA = xB;
    }

    // read = M_{L-2}@q = a + gs1*D(L-3,L-1)... (identical to round-8 epilogue)
    float readv = fmaf(gs2, d2, fmaf(gs1, d1, a));
    rds[i] = readv;
    __syncthreads();

    // r2[b][i] = read . rpW[:, i] + rpb[i]
    float acc = rpb[i];
    #pragma unroll 8
    for (int j = 0; j < 64; j++) acc = fmaf(rds[j], rpW[j * HH + i], acc);
    g_r2[b * HH + i] = acc;
}

// ---------------------------------------------------------------------------
// Kernel 3: out[b][v] = r2[b] . outW[:, v] + outb[v]
// Single-wave grid: 125 blocks x 512 thr; thread owns 2 v (float2) x 16 batches.
// ---------------------------------------------------------------------------
__global__ void __launch_bounds__(512, 2) k3_out(const float* __restrict__ outW,
                                                 const float* __restrict__ outb,
                                                 float* __restrict__ out) {
    __shared__ float r2s[64 * 64];
    const int tid = threadIdx.x;
    for (int idx = tid; idx < 64 * 64; idx += 512) r2s[idx] = g_r2[idx];
    __syncthreads();

    const int vl = tid & 127;          // float2 lane 0..127
    const int g  = tid >> 7;           // batch group 0..3
    const int v2 = blockIdx.x * 128 + vl;   // float2 column index (of 16000)
    const int b0 = g * 16;

    const float2* outW2 = (const float2*)outW;
    float2 acc[16];
    #pragma unroll
    for (int bb = 0; bb < 16; bb++) acc[bb] = make_float2(0.f, 0.f);

    #pragma unroll 8
    for (int j = 0; j < 64; j++) {
        float2 wv = outW2[j * (VV / 2) + v2];
        #pragma unroll
        for (int bb = 0; bb < 16; bb++) {
            float r = r2s[(b0 + bb) * 64 + j];
            acc[bb].x = fmaf(r, wv.x, acc[bb].x);
            acc[bb].y = fmaf(r, wv.y, acc[bb].y);
        }
    }
    float2 ob = ((const float2*)outb)[v2];
    float2* out2 = (float2*)out;
    #pragma unroll
    for (int bb = 0; bb < 16; bb++) {
        float2 r = acc[bb];
        r.x += ob.x; r.y += ob.y;
        out2[(b0 + bb) * (VV / 2) + v2] = r;
    }
}

// ---------------------------------------------------------------------------
extern "C" void kernel_launch(void* const* d_in, const int* in_sizes, int n_in,
                              void* d_out, int out_size) {
    const int*   seq   = (const int*)d_in[0];
    const float* embed = (const float*)d_in[1];
    const float* W1    = (const float*)d_in[2];
    const float* b1    = (const float*)d_in[3];
    const float* W2    = (const float*)d_in[4];
    const float* b2    = (const float*)d_in[5];
    const float* gamma = (const float*)d_in[6];
    const float* beta  = (const float*)d_in[7];
    const float* kpW   = (const float*)d_in[8];
    const float* rpW   = (const float*)d_in[9];
    const float* rpb   = (const float*)d_in[10];
    const float* outW  = (const float*)d_in[11];
    const float* outb  = (const float*)d_in[12];
    float* out = (float*)d_out;

    const int smem1 = (TOK * HPAD + HH * H2 + TOK * H2 + H2 * HH + HH * HH
                       + H2 + 3 * HH) * (int)sizeof(float);
    cudaFuncSetAttribute(k1_frontend, cudaFuncAttributeMaxDynamicSharedMemorySize, smem1);
    cudaFuncSetAttribute(k1_frontend, cudaFuncAttributePreferredSharedMemoryCarveout, 100);

    k1_frontend<<<(BB * LL) / TOK, 512, smem1>>>(seq, embed, W1, b1, W2, b2,
                                                 gamma, beta, kpW);
    k1b_meta<<<(BB * LL) / 8, 256>>>();
    k2_scan<<<BB, 64>>>(rpW, rpb);
    k3_out<<<VV / 256, 512>>>(outW, outb, out);
}